// round 3
// baseline (speedup 1.0000x reference)
#include <cuda_runtime.h>

#define NUM_GRAPHS   4096
#define NUM_ELEMENTS 120
#define EMB_DIM      64
#define HID_DIM      64

// Per-element energy table: table[e] = silu(emb[e] @ W1 + b1) @ W2 + b2
__device__ float g_table[NUM_ELEMENTS];

// ---------------------------------------------------------------------------
// Kernel A: build the 120-entry element-energy table.
// One block per element, 64 threads (one per hidden unit).
// ---------------------------------------------------------------------------
__global__ void build_table_kernel(const float* __restrict__ emb,
                                   const float* __restrict__ W1,
                                   const float* __restrict__ b1,
                                   const float* __restrict__ W2,
                                   const float* __restrict__ b2) {
    int e = blockIdx.x;     // element id [0,120)
    int j = threadIdx.x;    // hidden unit [0,64)

    float acc = 0.0f;
#pragma unroll
    for (int k = 0; k < EMB_DIM; ++k) {
        // emb[e][k] broadcasts across the block; W1[k][j] is coalesced in j.
        acc = fmaf(emb[e * EMB_DIM + k], W1[k * HID_DIM + j], acc);
    }
    acc += b1[j];
    // silu(x) = x * sigmoid(x)
    float s = acc / (1.0f + expf(-acc));
    float v = s * W2[j];

    // reduce 64 -> 1 (warp, then 2 partials)
#pragma unroll
    for (int off = 16; off > 0; off >>= 1)
        v += __shfl_down_sync(0xffffffffu, v, off);

    __shared__ float partial[2];
    if ((j & 31) == 0) partial[j >> 5] = v;
    __syncthreads();
    if (j == 0) g_table[e] = partial[0] + partial[1] + b2[0];
}

// ---------------------------------------------------------------------------
// Kernel Z: zero the forces region. forces = -grad_pos = 0 exactly, because
// the reference energy never reads pos. float4 stores, grid-stride.
// ---------------------------------------------------------------------------
__global__ void __launch_bounds__(256)
zero_forces_kernel(float* __restrict__ forces, long long nf) {
    long long nf4 = nf >> 2;                 // 3*n_atoms is divisible by 4 here? generic tail below
    float4* f4 = reinterpret_cast<float4*>(forces);
    long long stride = (long long)gridDim.x * blockDim.x;
    for (long long i = (long long)blockIdx.x * blockDim.x + threadIdx.x;
         i < nf4; i += stride)
        f4[i] = make_float4(0.f, 0.f, 0.f, 0.f);
    // scalar tail
    long long tail = nf4 << 2;
    for (long long i = tail + (long long)blockIdx.x * blockDim.x + threadIdx.x;
         i < nf; i += stride)
        forces[i] = 0.f;
}

// ---------------------------------------------------------------------------
// Kernel B: per-graph energy + atom counts. batch is sorted, so graph g's
// atoms are a contiguous run found by binary search; one warp per graph,
// no atomics, each output element written exactly once.
// ---------------------------------------------------------------------------
__global__ void __launch_bounds__(256)
energy_kernel(const int* __restrict__ z,
              const int* __restrict__ batch,
              float* __restrict__ out,   // [energy(4096) | forces(3N) | num_atoms(4096)]
              int n_atoms) {
    __shared__ float s_table[NUM_ELEMENTS];
    for (int i = threadIdx.x; i < NUM_ELEMENTS; i += blockDim.x)
        s_table[i] = g_table[i];
    __syncthreads();

    int gwarp = (int)((blockIdx.x * blockDim.x + threadIdx.x) >> 5);
    int lane  = threadIdx.x & 31;
    if (gwarp >= NUM_GRAPHS) return;

    // lower_bound on sorted batch: first index with batch[i] >= g
    auto lower_bound_g = [&](int g) -> int {
        int lo = 0, hi = n_atoms;
        while (lo < hi) {
            int mid = (lo + hi) >> 1;
            if (batch[mid] < g) lo = mid + 1; else hi = mid;
        }
        return lo;
    };
    int lo = lower_bound_g(gwarp);
    int hi = lower_bound_g(gwarp + 1);

    float sum = 0.0f;
    for (int i = lo + lane; i < hi; i += 32)
        sum += s_table[z[i]];

#pragma unroll
    for (int off = 16; off > 0; off >>= 1)
        sum += __shfl_down_sync(0xffffffffu, sum, off);

    if (lane == 0) {
        out[gwarp] = sum;                                         // energy
        out[NUM_GRAPHS + 3 * n_atoms + gwarp] = (float)(hi - lo); // num_atoms
    }
}

// ---------------------------------------------------------------------------
// kernel_launch — inputs per metadata order:
//   0: z (int32, N)   1: pos (f32, 3N)  2: batch (int32, N)
//   3: emb (f32)      4: W1 (f32)       5: b1 (f32)
//   6: W2 (f32)       7: b2 (f32)
// out: f32 [4096 + 3N + 4096]
// ---------------------------------------------------------------------------
extern "C" void kernel_launch(void* const* d_in, const int* in_sizes, int n_in,
                              void* d_out, int out_size) {
    const int*   z     = (const int*)  d_in[0];
    const int*   batch = (const int*)  d_in[2];
    const float* emb   = (const float*)d_in[3];
    const float* W1    = (const float*)d_in[4];
    const float* b1    = (const float*)d_in[5];
    const float* W2    = (const float*)d_in[6];
    const float* b2    = (const float*)d_in[7];
    float*       out   = (float*)d_out;
    int n_atoms = in_sizes[0];

    // forces = -grad_pos = exactly zero (energy is independent of pos)
    zero_forces_kernel<<<512, 256>>>(out + NUM_GRAPHS, 3LL * n_atoms);

    build_table_kernel<<<NUM_ELEMENTS, HID_DIM>>>(emb, W1, b1, W2, b2);

    // 4096 warps => 512 blocks x 256 threads
    energy_kernel<<<(NUM_GRAPHS * 32) / 256, 256>>>(z, batch, out, n_atoms);
}

// round 4
// speedup vs baseline: 1.6394x; 1.6394x over previous
#include <cuda_runtime.h>

#define NUM_GRAPHS   4096
#define NUM_ELEMENTS 120
#define EMB_DIM      64
#define HID_DIM      64

// Per-element energy table: table[e] = silu(emb[e] @ W1 + b1) @ W2 + b2
__device__ float g_table[NUM_ELEMENTS];

// ---------------------------------------------------------------------------
// Launch A (fused): blocks 0..119 additionally compute one table entry each
// (threads 0..63, one hidden unit per thread). ALL blocks grid-stride zero
// the entire output buffer [energy | forces | num_atoms] with float4 stores.
// forces = -grad_pos = exactly 0 (the reference energy never reads pos);
// energy/num_atoms regions must be 0 for launch B's atomics.
// ---------------------------------------------------------------------------
__global__ void __launch_bounds__(256)
prep_kernel(const float* __restrict__ emb,
            const float* __restrict__ W1,
            const float* __restrict__ b1,
            const float* __restrict__ W2,
            const float* __restrict__ b2,
            float* __restrict__ out,      // whole output buffer
            long long out_n)              // total floats in out
{
    // ---- table build: first 120 blocks, threads 0..63 ----
    if (blockIdx.x < NUM_ELEMENTS) {
        __shared__ float partial[2];
        int e = blockIdx.x;
        int j = threadIdx.x;
        if (j < HID_DIM) {
            float acc = 0.0f;
#pragma unroll
            for (int k = 0; k < EMB_DIM; ++k)
                acc = fmaf(emb[e * EMB_DIM + k], W1[k * HID_DIM + j], acc);
            acc += b1[j];
            float s = acc / (1.0f + expf(-acc));   // silu
            float v = s * W2[j];
#pragma unroll
            for (int off = 16; off > 0; off >>= 1)
                v += __shfl_down_sync(0xffffffffu, v, off);
            if ((j & 31) == 0) partial[j >> 5] = v;
        }
        __syncthreads();
        if (threadIdx.x == 0) g_table[e] = partial[0] + partial[1] + b2[0];
    }

    // ---- zero the whole output buffer (12.03 MB) ----
    long long n4 = out_n >> 2;                       // out_n divisible by 4 here
    float4* o4 = reinterpret_cast<float4*>(out);
    long long stride = (long long)gridDim.x * blockDim.x;
    for (long long i = (long long)blockIdx.x * blockDim.x + threadIdx.x;
         i < n4; i += stride)
        o4[i] = make_float4(0.f, 0.f, 0.f, 0.f);
    for (long long i = (n4 << 2) + (long long)blockIdx.x * blockDim.x + threadIdx.x;
         i < out_n; i += stride)
        out[i] = 0.f;
}

// ---------------------------------------------------------------------------
// Launch B: single linear pass over z/batch (int4 coalesced reads). Each
// thread handles 4 contiguous atoms, accumulating (g, sum, cnt) runs; an
// in-thread graph transition flushes the finished run with atomics (rare:
// ~4096 total). The final run of each thread enters a warp-wide SEGMENTED
// inclusive scan (batch sorted => equal-g lanes contiguous); the last lane
// of each segment does one atomicAdd pair. ~32K atomics over 4096 addresses.
// ---------------------------------------------------------------------------
__global__ void __launch_bounds__(256)
energy_scan_kernel(const int4* __restrict__ z4,
                   const int4* __restrict__ b4,
                   float* __restrict__ energy,     // out[0..4096)
                   float* __restrict__ counts,     // out[4096+3N ..)
                   int n4)                         // n_atoms/4
{
    __shared__ float s_table[NUM_ELEMENTS];
    for (int i = threadIdx.x; i < NUM_ELEMENTS; i += blockDim.x)
        s_table[i] = g_table[i];
    __syncthreads();

    const unsigned FULL = 0xffffffffu;
    int t    = blockIdx.x * blockDim.x + threadIdx.x;
    int lane = threadIdx.x & 31;

    int   runG   = -1;
    float runSum = 0.f;
    float runCnt = 0.f;
    bool  active = (t < n4);

    if (active) {
        int4 zz = z4[t];
        int4 bb = b4[t];

        runG = bb.x; runSum = s_table[zz.x]; runCnt = 1.f;

        if (bb.y == runG) { runSum += s_table[zz.y]; runCnt += 1.f; }
        else {
            atomicAdd(&energy[runG], runSum); atomicAdd(&counts[runG], runCnt);
            runG = bb.y; runSum = s_table[zz.y]; runCnt = 1.f;
        }
        if (bb.z == runG) { runSum += s_table[zz.z]; runCnt += 1.f; }
        else {
            atomicAdd(&energy[runG], runSum); atomicAdd(&counts[runG], runCnt);
            runG = bb.z; runSum = s_table[zz.z]; runCnt = 1.f;
        }
        if (bb.w == runG) { runSum += s_table[zz.w]; runCnt += 1.f; }
        else {
            atomicAdd(&energy[runG], runSum); atomicAdd(&counts[runG], runCnt);
            runG = bb.w; runSum = s_table[zz.w]; runCnt = 1.f;
        }
    }

    // warp segmented inclusive scan keyed by runG (non-decreasing over lanes)
#pragma unroll
    for (int d = 1; d < 32; d <<= 1) {
        float su = __shfl_up_sync(FULL, runSum, d);
        float cu = __shfl_up_sync(FULL, runCnt, d);
        int   gu = __shfl_up_sync(FULL, runG,   d);
        if (lane >= d && gu == runG) { runSum += su; runCnt += cu; }
    }
    int gnext = __shfl_down_sync(FULL, runG, 1);
    bool lastOfSeg = (lane == 31) || (gnext != runG);

    if (active && lastOfSeg && runG >= 0 && runG < NUM_GRAPHS) {
        atomicAdd(&energy[runG], runSum);
        atomicAdd(&counts[runG], runCnt);
    }
}

// ---------------------------------------------------------------------------
// kernel_launch — inputs per metadata order:
//   0: z (int32, N)   1: pos (f32, 3N)  2: batch (int32, N)
//   3: emb (f32)      4: W1 (f32)       5: b1 (f32)
//   6: W2 (f32)       7: b2 (f32)
// out: f32 [4096 + 3N + 4096]
// ---------------------------------------------------------------------------
extern "C" void kernel_launch(void* const* d_in, const int* in_sizes, int n_in,
                              void* d_out, int out_size) {
    const int*   z     = (const int*)  d_in[0];
    const int*   batch = (const int*)  d_in[2];
    const float* emb   = (const float*)d_in[3];
    const float* W1    = (const float*)d_in[4];
    const float* b1    = (const float*)d_in[5];
    const float* W2    = (const float*)d_in[6];
    const float* b2    = (const float*)d_in[7];
    float*       out   = (float*)d_out;
    int n_atoms = in_sizes[0];

    // Launch A: zero whole out buffer + build 120-entry table. 1184 CTAs =
    // 8 per SM on 148 SMs (full wave, no imbalance).
    prep_kernel<<<1184, 256>>>(emb, W1, b1, W2, b2, out, (long long)out_size);

    // Launch B: streaming segmented reduction over atoms (n_atoms % 4 == 0
    // for this problem; guarded in-kernel anyway).
    int n4 = n_atoms >> 2;
    int blocks = (n4 + 255) / 256;
    energy_scan_kernel<<<blocks, 256>>>(
        (const int4*)z, (const int4*)batch,
        out, out + NUM_GRAPHS + 3LL * n_atoms, n4);
}

// round 5
// speedup vs baseline: 1.6487x; 1.0057x over previous
#include <cuda_runtime.h>

#define NUM_GRAPHS   4096
#define NUM_ELEMENTS 120
#define EMB_DIM      64
#define HID_DIM      64

// Per-element energy table: table[e] = silu(emb[e] @ W1 + b1) @ W2 + b2
__device__ float g_table[NUM_ELEMENTS];

// ---------------------------------------------------------------------------
// Kernel A (small, serialized prefix): build the 120-entry table (blocks
// 0..119, threads 0..63) and zero ONLY the energy[4096] and counts[4096]
// regions that kernel B's atomics accumulate into. ~34 KB of stores total.
// ---------------------------------------------------------------------------
__global__ void __launch_bounds__(128)
prep_kernel(const float* __restrict__ emb,
            const float* __restrict__ W1,
            const float* __restrict__ b1,
            const float* __restrict__ W2,
            const float* __restrict__ b2,
            float4* __restrict__ energy4,   // out[0..4096) as float4 (1024)
            float4* __restrict__ counts4)   // out[4096+3N..) as float4 (1024)
{
    // table build
    if (blockIdx.x < NUM_ELEMENTS) {
        __shared__ float partial[2];
        int e = blockIdx.x;
        int j = threadIdx.x;
        if (j < HID_DIM) {
            float acc = 0.0f;
#pragma unroll
            for (int k = 0; k < EMB_DIM; ++k)
                acc = fmaf(emb[e * EMB_DIM + k], W1[k * HID_DIM + j], acc);
            acc += b1[j];
            float s = acc / (1.0f + expf(-acc));   // silu
            float v = s * W2[j];
#pragma unroll
            for (int off = 16; off > 0; off >>= 1)
                v += __shfl_down_sync(0xffffffffu, v, off);
            if ((j & 31) == 0) partial[j >> 5] = v;
        }
        __syncthreads();
        if (threadIdx.x == 0) g_table[e] = partial[0] + partial[1] + b2[0];
    }

    // zero energy + counts (1024 float4 each)
    int t = blockIdx.x * blockDim.x + threadIdx.x;
    int stride = gridDim.x * blockDim.x;
    float4 zf = make_float4(0.f, 0.f, 0.f, 0.f);
    for (int i = t; i < NUM_GRAPHS / 4; i += stride) {
        energy4[i] = zf;
        counts4[i] = zf;
    }
}

// ---------------------------------------------------------------------------
// Kernel B (fused): zero the 12 MB forces region AND do the streaming
// segmented reduction. Each thread: issue its 4 scan loads (8 atoms) first,
// then retire ~6 independent float4 zero-stores while the loads are in
// flight, then consume. Interior run transitions flush via atomics (~4096
// total); final runs merge via a warp segmented scan (batch sorted =>
// equal-g lanes contiguous), one atomicAdd pair per warp segment.
// ---------------------------------------------------------------------------
__global__ void __launch_bounds__(256)
scan_kernel(const int4* __restrict__ z4,
            const int4* __restrict__ b4,
            float4* __restrict__ forces4,   // out+4096 as float4
            long long nf4,                  // 3*n_atoms/4
            float* __restrict__ energy,     // out[0..4096)
            float* __restrict__ counts,     // out[4096+3N..)
            int n4)                         // n_atoms/4 (int4 count)
{
    __shared__ float s_table[NUM_ELEMENTS];
    for (int i = threadIdx.x; i < NUM_ELEMENTS; i += blockDim.x)
        s_table[i] = g_table[i];
    __syncthreads();

    const unsigned FULL = 0xffffffffu;
    int t    = blockIdx.x * blockDim.x + threadIdx.x;
    int lane = threadIdx.x & 31;
    long long stride = (long long)gridDim.x * blockDim.x;

    // ---- issue scan loads first (2 int4 pairs = 8 atoms per thread) ----
    int base = t * 2;                       // in int4 units
    bool a0 = (base     < n4);
    bool a1 = (base + 1 < n4);
    int4 zz0 = a0 ? z4[base]     : make_int4(0,0,0,0);
    int4 bb0 = a0 ? b4[base]     : make_int4(-1,-1,-1,-1);
    int4 zz1 = a1 ? z4[base + 1] : make_int4(0,0,0,0);
    int4 bb1 = a1 ? b4[base + 1] : make_int4(-1,-1,-1,-1);

    // ---- zero forces while loads are in flight (independent stores) ----
    {
        float4 zf = make_float4(0.f, 0.f, 0.f, 0.f);
        for (long long i = t; i < nf4; i += stride)
            forces4[i] = zf;
    }

    // ---- per-thread run accumulation over up to 8 atoms ----
    int   runG   = -1;
    float runSum = 0.f;
    float runCnt = 0.f;

    if (a0) {
        runG = bb0.x; runSum = s_table[zz0.x]; runCnt = 1.f;
        int gs[7] = { bb0.y, bb0.z, bb0.w, bb1.x, bb1.y, bb1.z, bb1.w };
        int zs[7] = { zz0.y, zz0.z, zz0.w, zz1.x, zz1.y, zz1.z, zz1.w };
        int navail = a1 ? 7 : 3;
#pragma unroll
        for (int k = 0; k < 7; ++k) {
            if (k < navail) {
                if (gs[k] == runG) { runSum += s_table[zs[k]]; runCnt += 1.f; }
                else {
                    atomicAdd(&energy[runG], runSum);
                    atomicAdd(&counts[runG], runCnt);
                    runG = gs[k]; runSum = s_table[zs[k]]; runCnt = 1.f;
                }
            }
        }
    }

    // ---- warp segmented inclusive scan keyed by runG ----
#pragma unroll
    for (int d = 1; d < 32; d <<= 1) {
        float su = __shfl_up_sync(FULL, runSum, d);
        float cu = __shfl_up_sync(FULL, runCnt, d);
        int   gu = __shfl_up_sync(FULL, runG,   d);
        if (lane >= d && gu == runG) { runSum += su; runCnt += cu; }
    }
    int gnext = __shfl_down_sync(FULL, runG, 1);
    bool lastOfSeg = (lane == 31) || (gnext != runG);

    if (lastOfSeg && runG >= 0 && runG < NUM_GRAPHS) {
        atomicAdd(&energy[runG], runSum);
        atomicAdd(&counts[runG], runCnt);
    }
}

// ---------------------------------------------------------------------------
// kernel_launch — inputs per metadata order:
//   0: z (int32, N)   1: pos (f32, 3N)  2: batch (int32, N)
//   3: emb (f32)      4: W1 (f32)       5: b1 (f32)
//   6: W2 (f32)       7: b2 (f32)
// out: f32 [energy 4096 | forces 3N | num_atoms 4096]
// ---------------------------------------------------------------------------
extern "C" void kernel_launch(void* const* d_in, const int* in_sizes, int n_in,
                              void* d_out, int out_size) {
    const int*   z     = (const int*)  d_in[0];
    const int*   batch = (const int*)  d_in[2];
    const float* emb   = (const float*)d_in[3];
    const float* W1    = (const float*)d_in[4];
    const float* b1    = (const float*)d_in[5];
    const float* W2    = (const float*)d_in[6];
    const float* b2    = (const float*)d_in[7];
    float*       out   = (float*)d_out;
    int n_atoms = in_sizes[0];

    float* energy = out;
    float* forces = out + NUM_GRAPHS;
    float* counts = out + NUM_GRAPHS + 3LL * n_atoms;

    // A: table + zero energy/counts only (~34 KB)
    prep_kernel<<<152, 128>>>(emb, W1, b1, W2, b2,
                              (float4*)energy, (float4*)counts);

    // B: fused forces-zero + segmented scan.
    // 8 atoms per thread: threads = ceil(n_atoms/8); 256/block.
    int n4 = n_atoms >> 2;                          // int4 count (n_atoms%4==0 here)
    int threads_needed = (n4 + 1) >> 1;             // 2 int4s per thread
    int blocks = (threads_needed + 255) / 256;      // = 489 for 1e6 atoms
    scan_kernel<<<blocks, 256>>>((const int4*)z, (const int4*)batch,
                                 (float4*)forces, 3LL * n_atoms / 4,
                                 energy, counts, n4);
}